// round 15
// baseline (speedup 1.0000x reference)
#include <cuda_runtime.h>
#include <math.h>

#define THREADS 512
#define ELEMS   8
#define NFAST   (THREADS * ELEMS)   // 4096
#define CAP     512                 // bracket candidate cap per side
#define NWARP   (THREADS / 32)

// Order-preserving float->uint key: monotonic increasing with float value.
__device__ __forceinline__ unsigned f2key(float v) {
    unsigned u = __float_as_uint(v);
    return u ^ (unsigned)(((int)u >> 31) | 0x80000000u);
}
__device__ __forceinline__ float key2f(unsigned key) {
    unsigned u = (key & 0x80000000u) ? (key ^ 0x80000000u) : ~key;
    return __uint_as_float(u);
}

// ========================= FAST kernel (n == 4096) ==========================
__global__ void __launch_bounds__(THREADS, 4)
wildcat_fast(const float* __restrict__ x, float* __restrict__ out,
             int kmax, int kmin, float alpha)
{
    __shared__ float     s_cand[2 * CAP];   // bracket candidates: top from 0, bottom from end
    __shared__ float     s_mini[2 * CAP];   // threshold-sub-bin elements
    __shared__ unsigned  s_hT[16], s_hB[16];
    __shared__ unsigned  s_cA, s_cB, s_c2[2];
    __shared__ int       s_cntH, s_cntL, s_mH, s_mL;
    __shared__ int       s_krH, s_krL, s_kr2H, s_kr2L;
    __shared__ int       s_selBinT, s_selBinB;
    __shared__ int       s_missT, s_missB, s_skipT, s_skipB, s_refine;
    __shared__ long long s_fb[4];           // loT, hiT, loB, hiB (fallback key bounds)
    __shared__ int       s_fc[4];           // cAloT, cAhiT, cBloB, cBhiB
    __shared__ unsigned  s_selH, s_selL;
    __shared__ int       s_resH, s_resL;
    __shared__ float     s_redf[2][NWARP];

    const int tid  = threadIdx.x;
    const int lane = tid & 31;
    const int wid  = tid >> 5;
    const float* __restrict__ xr = x + (long long)blockIdx.x * NFAST;

    // ---- load 8 elements into registers (the only full-row memory pass) -----
    float v[ELEMS];
    {
        const float4* __restrict__ xr4 = (const float4*)xr;
        float4 t0 = xr4[tid];
        float4 t1 = xr4[tid + THREADS];
        v[0] = t0.x; v[1] = t0.y; v[2] = t0.z; v[3] = t0.w;
        v[4] = t1.x; v[5] = t1.y; v[6] = t1.z; v[7] = t1.w;
    }
    if (tid < 16) s_hT[tid] = 0;
    else if (tid < 32) s_hB[tid - 16] = 0;
    if (tid == 0) {
        s_cA = 0; s_cB = 0; s_cntH = 0; s_cntL = 0; s_mH = 0; s_mL = 0;
        s_skipT = 0; s_skipB = 0;
    }
    __syncthreads();

    const float PT_HI = 0.94f, PT_LO = 0.74f;      // top bracket (PT_LO, PT_HI]
    const float PB_LO = -0.94f, PB_HI = -0.74f;    // bottom bracket [PB_LO, PB_HI)

    // ===== single fused sweep: strict sums + exact counts + aggregated
    //       bracket compaction ================================================
    float sumT = 0.0f, sumB = 0.0f;
    {
        unsigned cA = 0, cB = 0;
        #pragma unroll
        for (int j = 0; j < ELEMS; j++) {
            float f = v[j];
            bool hiT = f > PT_HI;
            bool inH = (f > PT_LO) && !hiT;
            bool loB = f < PB_LO;
            bool inL = (f < PB_HI) && !loB;
            if (hiT) { sumT += f; cA++; }
            if (loB) { sumB += f; cB++; }

            unsigned mH = __ballot_sync(0xFFFFFFFFu, inH);
            if (inH) {
                int ldr = __ffs(mH) - 1;
                int base;
                if (lane == ldr) base = atomicAdd(&s_cntH, __popc(mH));
                base = __shfl_sync(mH, base, ldr);
                int p = base + __popc(mH & ((1u << lane) - 1u));
                if (p < CAP) s_cand[p] = f;
            }
            unsigned mL = __ballot_sync(0xFFFFFFFFu, inL);
            if (inL) {
                int ldr = __ffs(mL) - 1;
                int base;
                if (lane == ldr) base = atomicAdd(&s_cntL, __popc(mL));
                base = __shfl_sync(mL, base, ldr);
                int p = base + __popc(mL & ((1u << lane) - 1u));
                if (p < CAP) s_cand[2 * CAP - 1 - p] = f;
            }
        }
        cA = __reduce_add_sync(0xFFFFFFFFu, cA);
        cB = __reduce_add_sync(0xFFFFFFFFu, cB);
        if (lane == 0) { atomicAdd(&s_cA, cA); atomicAdd(&s_cB, cB); }
    }
    __syncthreads();

    // ---- exact rank check: does the kth element land inside the bracket? ----
    if (tid == 0) {
        int kr = kmax - (int)s_cA;
        s_krH = kr;
        s_missT = (kr <= 0 || kr > s_cntH || s_cntH > CAP) ? 1 : 0;
    }
    if (tid == 32) {
        int kr = kmin - (int)s_cB;
        s_krL = kr;
        s_missB = (kr <= 0 || kr > s_cntL || s_cntL > CAP) ? 1 : 0;
    }
    __syncthreads();

    const int cnH = min(s_cntH, CAP), cnL = min(s_cntL, CAP);
    const int missT = s_missT, missB = s_missB;

    // ===== sub-bin histogram over candidates (16 bins, arithmetic binning) ====
    if (!missT) {
        for (int c = tid; c < cnH; c += THREADS) {
            float f = s_cand[c];
            int b = (int)((f - PT_LO) * 80.0f); b = max(0, min(15, b));
            atomicAdd(&s_hT[b], 1u);
        }
    }
    if (!missB) {
        for (int c = tid; c < cnL; c += THREADS) {
            float f = s_cand[2 * CAP - 1 - c];
            int b = (int)((f - PB_LO) * 80.0f); b = max(0, min(15, b));
            atomicAdd(&s_hB[b], 1u);
        }
    }
    __syncthreads();
    if (tid == 0 && !missT) {
        int kr = s_krH, cum = 0, sel = 0, kr2 = kr;
        for (int b = 15; b >= 0; --b) {
            int c = (int)s_hT[b];
            if (cum + c >= kr) { sel = b; kr2 = kr - cum; break; }
            cum += c;
        }
        s_selBinT = sel; s_kr2H = kr2;
    }
    if (tid == 32 && !missB) {
        int kr = s_krL, cum = 0, sel = 15, kr2 = kr;
        for (int b = 0; b < 16; ++b) {
            int c = (int)s_hB[b];
            if (cum + c >= kr) { sel = b; kr2 = kr - cum; break; }
            cum += c;
        }
        s_selBinB = sel; s_kr2L = kr2;
    }
    __syncthreads();

    // ===== mini pass: bank above/below-sub-bin sums, gather threshold sub-bin =
    if (!missT) {
        const int sel = s_selBinT;
        for (int c = tid; c < cnH; c += THREADS) {
            float f = s_cand[c];
            int b = (int)((f - PT_LO) * 80.0f); b = max(0, min(15, b));
            if (b > sel) sumT += f;
            else if (b == sel) { int p = atomicAdd(&s_mH, 1); s_mini[p] = f; }
        }
    }
    if (!missB) {
        const int sel = s_selBinB;
        for (int c = tid; c < cnL; c += THREADS) {
            float f = s_cand[2 * CAP - 1 - c];
            int b = (int)((f - PB_LO) * 80.0f); b = max(0, min(15, b));
            if (b < sel) sumB += f;
            else if (b == sel) { int p = atomicAdd(&s_mL, 1); s_mini[2 * CAP - 1 - p] = f; }
        }
    }

    // ===== exact key-space fallback for missed sides (cold, block-uniform) ====
    if (missT || missB) {
        if (tid == 0) {
            s_fb[0] = -1; s_fb[1] = 0xFFFFFFFFLL;  s_fc[0] = NFAST; s_fc[1] = 0;
            s_fb[2] = 0;  s_fb[3] = 0x100000000LL; s_fc[2] = 0;     s_fc[3] = NFAST;
            s_refine = 1;
        }
        __syncthreads();
        while (s_refine) {
            if (tid < 2) s_c2[tid] = 0;
            const long long midT = (s_fb[0] + s_fb[1]) >> 1;
            const long long midB = (s_fb[2] + s_fb[3]) >> 1;
            __syncthreads();
            unsigned ct = 0, cb = 0;
            #pragma unroll
            for (int j = 0; j < ELEMS; j++) {
                long long k = (long long)f2key(v[j]);
                ct += (k > midT);
                cb += (k < midB);
            }
            ct = __reduce_add_sync(0xFFFFFFFFu, ct);
            cb = __reduce_add_sync(0xFFFFFFFFu, cb);
            if (lane == 0) { atomicAdd(&s_c2[0], ct); atomicAdd(&s_c2[1], cb); }
            __syncthreads();
            if (tid == 0) {
                if (missT && (s_fc[0] - s_fc[1] > CAP) && (s_fb[1] - s_fb[0] > 1)) {
                    int c = (int)s_c2[0];
                    if (c >= kmax) { s_fb[0] = midT; s_fc[0] = c; }
                    else           { s_fb[1] = midT; s_fc[1] = c; }
                }
                if (missB && (s_fc[3] - s_fc[2] > CAP) && (s_fb[3] - s_fb[2] > 1)) {
                    int c = (int)s_c2[1];
                    if (c >= kmin) { s_fb[3] = midB; s_fc[3] = c; }
                    else           { s_fb[2] = midB; s_fc[2] = c; }
                }
                bool nT = missT && (s_fc[0] - s_fc[1] > CAP) && (s_fb[1] - s_fb[0] > 1);
                bool nB = missB && (s_fc[3] - s_fc[2] > CAP) && (s_fb[3] - s_fb[2] > 1);
                s_refine = (nT || nB) ? 1 : 0;
            }
            __syncthreads();
        }
        if (missT) {
            sumT = 0.0f;                               // recompute side exactly
            const long long lo = s_fb[0], hi = s_fb[1];
            const bool w1 = (hi - lo) == 1;
            if (tid == 0) {
                s_kr2H = kmax - s_fc[1];
                if (w1) { s_skipT = 1; s_selH = (unsigned)hi; s_resH = kmax - s_fc[1]; }
            }
            #pragma unroll
            for (int j = 0; j < ELEMS; j++) {
                float f = v[j];
                long long k = (long long)f2key(f);
                if (k > hi) sumT += f;
                else if (!w1 && k > lo) { int p = atomicAdd(&s_mH, 1); if (p < CAP) s_mini[p] = f; }
            }
        }
        if (missB) {
            sumB = 0.0f;
            const long long lo = s_fb[2], hi = s_fb[3];
            const bool w1 = (hi - lo) == 1;
            if (tid == 0) {
                s_kr2L = kmin - s_fc[2];
                if (w1) { s_skipB = 1; s_selL = (unsigned)lo; s_resL = kmin - s_fc[2]; }
            }
            #pragma unroll
            for (int j = 0; j < ELEMS; j++) {
                float f = v[j];
                long long k = (long long)f2key(f);
                if (k < lo) sumB += f;
                else if (!w1 && k < hi) { int p = atomicAdd(&s_mL, 1); if (p < CAP) s_mini[2 * CAP - 1 - p] = f; }
            }
        }
    }
    __syncthreads();

    // ===== quadratic rank-select over mini lists (~15-25 elements) ============
    const int mH = min(s_mH, CAP), mL = min(s_mL, CAP);
    if (!s_skipT) {
        const int kr = s_kr2H;
        for (int c = tid; c < mH; c += THREADS) {
            float fc = s_mini[c];
            unsigned kc = f2key(fc);
            int cg = 0, ce = 0;
            for (int j = 0; j < mH; j++) {
                unsigned kj = f2key(s_mini[j]);
                cg += (kj > kc);
                ce += (kj == kc);
            }
            if (cg + ce < kr) sumT += fc;                   // strictly above threshold
            if (cg < kr && kr <= cg + ce) { s_selH = kc; s_resH = kr - cg; }
        }
    }
    if (!s_skipB) {
        const int kr = s_kr2L;
        for (int c = tid; c < mL; c += THREADS) {
            float fc = s_mini[2 * CAP - 1 - c];
            unsigned kc = f2key(fc);
            int cl = 0, ce = 0;
            for (int j = 0; j < mL; j++) {
                unsigned kj = f2key(s_mini[2 * CAP - 1 - j]);
                cl += (kj < kc);
                ce += (kj == kc);
            }
            if (cl + ce < kr) sumB += fc;                   // strictly below threshold
            if (cl < kr && kr <= cl + ce) { s_selL = kc; s_resL = kr - cl; }
        }
    }
    __syncthreads();

    // ---- block reduction + epilogue ------------------------------------------
    #pragma unroll
    for (int o = 16; o > 0; o >>= 1) {
        sumT += __shfl_xor_sync(0xFFFFFFFFu, sumT, o);
        sumB += __shfl_xor_sync(0xFFFFFFFFu, sumB, o);
    }
    if (lane == 0) { s_redf[0][wid] = sumT; s_redf[1][wid] = sumB; }
    __syncthreads();

    if (tid == 0) {
        float st = 0.0f, sb = 0.0f;
        #pragma unroll
        for (int w = 0; w < NWARP; ++w) { st += s_redf[0][w]; sb += s_redf[1][w]; }
        st += (float)s_resH * key2f(s_selH);    // exact tie handling
        sb += (float)s_resL * key2f(s_selL);
        out[blockIdx.x] = st / (float)kmax + (alpha / (float)kmin) * sb;
    }
}

// ================= GENERIC fallback (any n) — proven R8 path ================
#define GTHREADS 256

template<int NB, bool DESC>
__device__ __forceinline__ void resolve_small(const unsigned* __restrict__ hist, int krem,
                                              int lane, unsigned &bin, int &krem_out)
{
    constexpr int BPL = NB / 32;
    unsigned s = 0;
    #pragma unroll
    for (int j = 0; j < BPL; j++) {
        int b = DESC ? (NB - 1 - (lane * BPL + j)) : (lane * BPL + j);
        s += hist[b];
    }
    unsigned p = s;
    #pragma unroll
    for (int o = 1; o < 32; o <<= 1) {
        unsigned t = __shfl_up_sync(0xFFFFFFFFu, p, o);
        if (lane >= o) p += t;
    }
    unsigned excl = p - s;
    bool cross = (excl < (unsigned)krem) && (p >= (unsigned)krem);
    unsigned m = __ballot_sync(0xFFFFFFFFu, cross);
    int src = __ffs(m) - 1;
    unsigned bsel = 0; int k2 = 0;
    if (cross) {
        unsigned cum = excl;
        #pragma unroll
        for (int j = 0; j < BPL; j++) {
            int b = DESC ? (NB - 1 - (lane * BPL + j)) : (lane * BPL + j);
            unsigned c = hist[b];
            if (cum + c >= (unsigned)krem) { bsel = (unsigned)b; k2 = krem - (int)cum; break; }
            cum += c;
        }
    }
    bin = __shfl_sync(0xFFFFFFFFu, bsel, src);
    krem_out = __shfl_sync(0xFFFFFFFFu, k2, src);
}

template<bool DESC>
__device__ __forceinline__ void resolve_big(const unsigned* __restrict__ hist, int krem,
                                            int lane, unsigned &bin, int &krem_out)
{
    const uint4* h4 = (const uint4*)hist;
    unsigned s = 0;
    #pragma unroll
    for (int j = 0; j < 32; j++) {
        uint4 c = h4[lane * 32 + j];
        s += c.x + c.y + c.z + c.w;
    }
    unsigned p = s;
    if (DESC) {
        #pragma unroll
        for (int o = 1; o < 32; o <<= 1) {
            unsigned t = __shfl_down_sync(0xFFFFFFFFu, p, o);
            if (lane + o < 32) p += t;
        }
    } else {
        #pragma unroll
        for (int o = 1; o < 32; o <<= 1) {
            unsigned t = __shfl_up_sync(0xFFFFFFFFu, p, o);
            if (lane >= o) p += t;
        }
    }
    unsigned excl = p - s;
    bool cross = (excl < (unsigned)krem) && (p >= (unsigned)krem);
    unsigned m = __ballot_sync(0xFFFFFFFFu, cross);
    int src = __ffs(m) - 1;
    unsigned bsel = 0; int k2 = 0;
    if (cross) {
        unsigned cum = excl;
        if (DESC) {
            for (int b = lane * 128 + 127; b >= lane * 128; --b) {
                unsigned c = hist[b];
                if (cum + c >= (unsigned)krem) { bsel = (unsigned)b; k2 = krem - (int)cum; break; }
                cum += c;
            }
        } else {
            for (int b = lane * 128; b < lane * 128 + 128; ++b) {
                unsigned c = hist[b];
                if (cum + c >= (unsigned)krem) { bsel = (unsigned)b; k2 = krem - (int)cum; break; }
                cum += c;
            }
        }
    }
    bin = __shfl_sync(0xFFFFFFFFu, bsel, src);
    krem_out = __shfl_sync(0xFFFFFFFFu, k2, src);
}

__global__ void __launch_bounds__(GTHREADS, 8)
wildcat_generic(const float* __restrict__ x, float* __restrict__ out,
                int n, int kmax, int kmin, float alpha)
{
    __shared__ unsigned s_mem[4096];
    __shared__ unsigned s_subh[512];
    __shared__ unsigned s_selH, s_selL;
    __shared__ int      s_kremH, s_kremL, s_cntH, s_cntL;
    __shared__ float    s_red[2][GTHREADS / 32];
    float* s_val = (float*)s_mem;

    const int tid  = threadIdx.x;
    const int lane = tid & 31;
    const int wid  = tid >> 5;
    const float* __restrict__ xr = x + (long long)blockIdx.x * n;

    for (int b = tid; b < 4096; b += GTHREADS) s_mem[b] = 0;
    if (tid == 0) { s_cntH = 0; s_cntL = 0; }
    __syncthreads();

    for (int i = tid; i < n; i += GTHREADS)
        atomicAdd(&s_mem[f2key(xr[i]) >> 20], 1u);
    __syncthreads();

    if (wid == 0) {
        unsigned b; int k2;
        resolve_big<true>(s_mem, kmax, lane, b, k2);
        if (lane == 0) { s_selH = b; s_kremH = k2; }
    } else if (wid == 1) {
        unsigned b; int k2;
        resolve_big<false>(s_mem, kmin, lane, b, k2);
        if (lane == 0) { s_selL = b; s_kremL = k2; }
    }
    __syncthreads();
    const unsigned binH = s_selH, binL = s_selL;
    const bool sameBin = (binH == binL);
    __syncthreads();

    float sumT = 0.0f, sumB = 0.0f;
    for (int i = tid; i < n; i += GTHREADS) {
        float f = xr[i];
        unsigned b = f2key(f) >> 20;
        if (b > binH) sumT += f;
        if (b < binL) sumB += f;
        if (b == binH) { int p = atomicAdd(&s_cntH, 1); s_val[p] = f; }
        else if (b == binL) { int p = atomicAdd(&s_cntL, 1); s_val[4095 - p] = f; }
    }
    __syncthreads();
    const int cntH = min(s_cntH, 4096);
    const int cntL = sameBin ? cntH : min(s_cntL, 4096);

    #pragma unroll 1
    for (int l = 0; l < 3; l++) {
        const int fs = (l == 0) ? 20 : (l == 1) ? 12 : 6;
        const int sh = (l == 0) ? 12 : (l == 1) ? 6 : 0;
        const unsigned mk = (l == 0) ? 0xFFu : 0x3Fu;
        const int nb = (l == 0) ? 256 : 64;
        const unsigned pH = s_selH, pL = s_selL;
        if (tid < nb) { s_subh[tid] = 0; s_subh[tid + 256] = 0; }
        __syncthreads();
        for (int t = tid; t < cntH; t += GTHREADS) {
            unsigned key = f2key(s_val[t]);
            if ((key >> fs) == pH) atomicAdd(&s_subh[(key >> sh) & mk], 1u);
        }
        for (int t = tid; t < cntL; t += GTHREADS) {
            float f = sameBin ? s_val[t] : s_val[4095 - t];
            unsigned key = f2key(f);
            if ((key >> fs) == pL) atomicAdd(&s_subh[256 + ((key >> sh) & mk)], 1u);
        }
        __syncthreads();
        if (wid == 0) {
            unsigned b; int k2;
            if (nb == 256) resolve_small<256, true>(s_subh, s_kremH, lane, b, k2);
            else           resolve_small<64,  true>(s_subh, s_kremH, lane, b, k2);
            if (lane == 0) { s_selH = (pH << ((l == 0) ? 8 : 6)) | b; s_kremH = k2; }
        } else if (wid == 1) {
            unsigned b; int k2;
            if (nb == 256) resolve_small<256, false>(s_subh + 256, s_kremL, lane, b, k2);
            else           resolve_small<64,  false>(s_subh + 256, s_kremL, lane, b, k2);
            if (lane == 0) { s_selL = (pL << ((l == 0) ? 8 : 6)) | b; s_kremL = k2; }
        }
        __syncthreads();
    }

    const unsigned keyH = s_selH, keyL = s_selL;
    for (int t = tid; t < cntH; t += GTHREADS) {
        float f = s_val[t];
        if (f2key(f) > keyH) sumT += f;
    }
    for (int t = tid; t < cntL; t += GTHREADS) {
        float f = sameBin ? s_val[t] : s_val[4095 - t];
        if (f2key(f) < keyL) sumB += f;
    }
    #pragma unroll
    for (int o = 16; o > 0; o >>= 1) {
        sumT += __shfl_xor_sync(0xFFFFFFFFu, sumT, o);
        sumB += __shfl_xor_sync(0xFFFFFFFFu, sumB, o);
    }
    if (lane == 0) { s_red[0][wid] = sumT; s_red[1][wid] = sumB; }
    __syncthreads();
    if (tid == 0) {
        float st = 0.0f, sb = 0.0f;
        #pragma unroll
        for (int w = 0; w < GTHREADS / 32; ++w) { st += s_red[0][w]; sb += s_red[1][w]; }
        st += (float)s_kremH * key2f(keyH);
        sb += (float)s_kremL * key2f(keyL);
        out[blockIdx.x] = st / (float)kmax + (alpha / (float)kmin) * sb;
    }
}

extern "C" void kernel_launch(void* const* d_in, const int* in_sizes, int n_in,
                              void* d_out, int out_size)
{
    const float* x = (const float*)d_in[0];
    float* out = (float*)d_out;

    const int rows = out_size;                 // 32*512 = 16384
    const int n = in_sizes[0] / rows;          // 4096
    int kmax = (int)lrintf(0.2f * (float)n);   // int(round(0.2*n)) = 819
    int kmin = (int)lrintf(0.2f * (float)n);
    if (kmax < 1) kmax = 1;
    if (kmin < 1) kmin = 1;

    if (n == NFAST)
        wildcat_fast<<<rows, THREADS>>>(x, out, kmax, kmin, 0.7f);
    else
        wildcat_generic<<<rows, GTHREADS>>>(x, out, n, kmax, kmin, 0.7f);
}

// round 16
// speedup vs baseline: 1.2479x; 1.2479x over previous
#include <cuda_runtime.h>
#include <math.h>

#define THREADS 512
#define ELEMS   8
#define NFAST   (THREADS * ELEMS)   // 4096
#define CAP     512                 // bracket candidate cap per side
#define NWARP   (THREADS / 32)

// Order-preserving float->uint key: monotonic increasing with float value.
__device__ __forceinline__ unsigned f2key(float v) {
    unsigned u = __float_as_uint(v);
    return u ^ (unsigned)(((int)u >> 31) | 0x80000000u);
}
__device__ __forceinline__ float key2f(unsigned key) {
    unsigned u = (key & 0x80000000u) ? (key ^ 0x80000000u) : ~key;
    return __uint_as_float(u);
}

// ========================= FAST kernel (n == 4096) ==========================
__global__ void __launch_bounds__(THREADS, 4)
wildcat_fast(const float* __restrict__ x, float* __restrict__ out,
             int kmax, int kmin, float alpha)
{
    __shared__ float     s_cand[2 * CAP];   // bracket candidates: top from 0, bottom from end
    __shared__ float     s_mini[2 * CAP];   // threshold-sub-bin elements
    __shared__ unsigned  s_hT[16], s_hB[16];
    __shared__ unsigned  s_cA, s_cB, s_c2[2];
    __shared__ int       s_cntH, s_cntL, s_mH, s_mL;
    __shared__ int       s_krH, s_krL, s_kr2H, s_kr2L;
    __shared__ int       s_selBinT, s_selBinB;
    __shared__ int       s_missT, s_missB, s_skipT, s_skipB, s_refine;
    __shared__ long long s_fb[4];           // loT, hiT, loB, hiB (fallback key bounds)
    __shared__ int       s_fc[4];           // cAloT, cAhiT, cBloB, cBhiB
    __shared__ unsigned  s_selH, s_selL;
    __shared__ int       s_resH, s_resL;
    __shared__ float     s_redf[2][NWARP];

    const int tid  = threadIdx.x;
    const int lane = tid & 31;
    const int wid  = tid >> 5;
    const float* __restrict__ xr = x + (long long)blockIdx.x * NFAST;

    // ---- load 8 elements into registers (the only full-row memory pass) -----
    float v[ELEMS];
    {
        const float4* __restrict__ xr4 = (const float4*)xr;
        float4 t0 = xr4[tid];
        float4 t1 = xr4[tid + THREADS];
        v[0] = t0.x; v[1] = t0.y; v[2] = t0.z; v[3] = t0.w;
        v[4] = t1.x; v[5] = t1.y; v[6] = t1.z; v[7] = t1.w;
    }
    if (tid < 16) s_hT[tid] = 0;
    else if (tid < 32) s_hB[tid - 16] = 0;
    if (tid == 0) {
        s_cA = 0; s_cB = 0; s_cntH = 0; s_cntL = 0; s_mH = 0; s_mL = 0;
        s_skipT = 0; s_skipB = 0;
    }
    __syncthreads();

    const float PT_HI = 0.94f, PT_LO = 0.74f;      // top bracket (PT_LO, PT_HI]
    const float PB_LO = -0.94f, PB_HI = -0.74f;    // bottom bracket [PB_LO, PB_HI)

    // ===== single fused sweep: strict sums + exact counts + bracket compaction
    //       (plain atomics on the RARE branch — no per-element warp intrinsics)
    float sumT = 0.0f, sumB = 0.0f;
    {
        unsigned cA = 0, cB = 0;
        #pragma unroll
        for (int j = 0; j < ELEMS; j++) {
            float f = v[j];
            if (f > PT_HI) { sumT += f; cA++; }
            else if (f > PT_LO) { int p = atomicAdd(&s_cntH, 1); if (p < CAP) s_cand[p] = f; }
            if (f < PB_LO) { sumB += f; cB++; }
            else if (f < PB_HI) { int p = atomicAdd(&s_cntL, 1); if (p < CAP) s_cand[2 * CAP - 1 - p] = f; }
        }
        cA = __reduce_add_sync(0xFFFFFFFFu, cA);
        cB = __reduce_add_sync(0xFFFFFFFFu, cB);
        if (lane == 0) { atomicAdd(&s_cA, cA); atomicAdd(&s_cB, cB); }
    }
    __syncthreads();

    // ---- exact rank check: does the kth element land inside the bracket? ----
    if (tid == 0) {
        int kr = kmax - (int)s_cA;
        s_krH = kr;
        s_missT = (kr <= 0 || kr > s_cntH || s_cntH > CAP) ? 1 : 0;
    }
    if (tid == 32) {
        int kr = kmin - (int)s_cB;
        s_krL = kr;
        s_missB = (kr <= 0 || kr > s_cntL || s_cntL > CAP) ? 1 : 0;
    }
    __syncthreads();

    const int cnH = min(s_cntH, CAP), cnL = min(s_cntL, CAP);
    const int missT = s_missT, missB = s_missB;

    // ===== sub-bin histogram over candidates (16 bins, arithmetic binning) ====
    if (!missT) {
        for (int c = tid; c < cnH; c += THREADS) {
            float f = s_cand[c];
            int b = (int)((f - PT_LO) * 80.0f); b = max(0, min(15, b));
            atomicAdd(&s_hT[b], 1u);
        }
    }
    if (!missB) {
        for (int c = tid; c < cnL; c += THREADS) {
            float f = s_cand[2 * CAP - 1 - c];
            int b = (int)((f - PB_LO) * 80.0f); b = max(0, min(15, b));
            atomicAdd(&s_hB[b], 1u);
        }
    }
    __syncthreads();
    if (tid == 0 && !missT) {
        int kr = s_krH, cum = 0, sel = 0, kr2 = kr;
        for (int b = 15; b >= 0; --b) {
            int c = (int)s_hT[b];
            if (cum + c >= kr) { sel = b; kr2 = kr - cum; break; }
            cum += c;
        }
        s_selBinT = sel; s_kr2H = kr2;
    }
    if (tid == 32 && !missB) {
        int kr = s_krL, cum = 0, sel = 15, kr2 = kr;
        for (int b = 0; b < 16; ++b) {
            int c = (int)s_hB[b];
            if (cum + c >= kr) { sel = b; kr2 = kr - cum; break; }
            cum += c;
        }
        s_selBinB = sel; s_kr2L = kr2;
    }
    __syncthreads();

    // ===== mini pass: bank above/below-sub-bin sums, gather threshold sub-bin =
    if (!missT) {
        const int sel = s_selBinT;
        for (int c = tid; c < cnH; c += THREADS) {
            float f = s_cand[c];
            int b = (int)((f - PT_LO) * 80.0f); b = max(0, min(15, b));
            if (b > sel) sumT += f;
            else if (b == sel) { int p = atomicAdd(&s_mH, 1); s_mini[p] = f; }
        }
    }
    if (!missB) {
        const int sel = s_selBinB;
        for (int c = tid; c < cnL; c += THREADS) {
            float f = s_cand[2 * CAP - 1 - c];
            int b = (int)((f - PB_LO) * 80.0f); b = max(0, min(15, b));
            if (b < sel) sumB += f;
            else if (b == sel) { int p = atomicAdd(&s_mL, 1); s_mini[2 * CAP - 1 - p] = f; }
        }
    }

    // ===== exact key-space fallback for missed sides (cold, block-uniform) ====
    if (missT || missB) {
        if (tid == 0) {
            s_fb[0] = -1; s_fb[1] = 0xFFFFFFFFLL;  s_fc[0] = NFAST; s_fc[1] = 0;
            s_fb[2] = 0;  s_fb[3] = 0x100000000LL; s_fc[2] = 0;     s_fc[3] = NFAST;
            s_refine = 1;
        }
        __syncthreads();
        while (s_refine) {
            if (tid < 2) s_c2[tid] = 0;
            const long long midT = (s_fb[0] + s_fb[1]) >> 1;
            const long long midB = (s_fb[2] + s_fb[3]) >> 1;
            __syncthreads();
            unsigned ct = 0, cb = 0;
            #pragma unroll
            for (int j = 0; j < ELEMS; j++) {
                long long k = (long long)f2key(v[j]);
                ct += (k > midT);
                cb += (k < midB);
            }
            ct = __reduce_add_sync(0xFFFFFFFFu, ct);
            cb = __reduce_add_sync(0xFFFFFFFFu, cb);
            if (lane == 0) { atomicAdd(&s_c2[0], ct); atomicAdd(&s_c2[1], cb); }
            __syncthreads();
            if (tid == 0) {
                if (missT && (s_fc[0] - s_fc[1] > CAP) && (s_fb[1] - s_fb[0] > 1)) {
                    int c = (int)s_c2[0];
                    if (c >= kmax) { s_fb[0] = midT; s_fc[0] = c; }
                    else           { s_fb[1] = midT; s_fc[1] = c; }
                }
                if (missB && (s_fc[3] - s_fc[2] > CAP) && (s_fb[3] - s_fb[2] > 1)) {
                    int c = (int)s_c2[1];
                    if (c >= kmin) { s_fb[3] = midB; s_fc[3] = c; }
                    else           { s_fb[2] = midB; s_fc[2] = c; }
                }
                bool nT = missT && (s_fc[0] - s_fc[1] > CAP) && (s_fb[1] - s_fb[0] > 1);
                bool nB = missB && (s_fc[3] - s_fc[2] > CAP) && (s_fb[3] - s_fb[2] > 1);
                s_refine = (nT || nB) ? 1 : 0;
            }
            __syncthreads();
        }
        if (missT) {
            sumT = 0.0f;                               // recompute side exactly
            const long long lo = s_fb[0], hi = s_fb[1];
            const bool w1 = (hi - lo) == 1;
            if (tid == 0) {
                s_kr2H = kmax - s_fc[1];
                if (w1) { s_skipT = 1; s_selH = (unsigned)hi; s_resH = kmax - s_fc[1]; }
            }
            #pragma unroll
            for (int j = 0; j < ELEMS; j++) {
                float f = v[j];
                long long k = (long long)f2key(f);
                if (k > hi) sumT += f;
                else if (!w1 && k > lo) { int p = atomicAdd(&s_mH, 1); if (p < CAP) s_mini[p] = f; }
            }
        }
        if (missB) {
            sumB = 0.0f;
            const long long lo = s_fb[2], hi = s_fb[3];
            const bool w1 = (hi - lo) == 1;
            if (tid == 0) {
                s_kr2L = kmin - s_fc[2];
                if (w1) { s_skipB = 1; s_selL = (unsigned)lo; s_resL = kmin - s_fc[2]; }
            }
            #pragma unroll
            for (int j = 0; j < ELEMS; j++) {
                float f = v[j];
                long long k = (long long)f2key(f);
                if (k < lo) sumB += f;
                else if (!w1 && k < hi) { int p = atomicAdd(&s_mL, 1); if (p < CAP) s_mini[2 * CAP - 1 - p] = f; }
            }
        }
    }
    __syncthreads();

    // ===== quadratic rank-select over mini lists (~15-25 elements) ============
    const int mH = min(s_mH, CAP), mL = min(s_mL, CAP);
    if (!s_skipT) {
        const int kr = s_kr2H;
        for (int c = tid; c < mH; c += THREADS) {
            float fc = s_mini[c];
            unsigned kc = f2key(fc);
            int cg = 0, ce = 0;
            for (int j = 0; j < mH; j++) {
                unsigned kj = f2key(s_mini[j]);
                cg += (kj > kc);
                ce += (kj == kc);
            }
            if (cg + ce < kr) sumT += fc;                   // strictly above threshold
            if (cg < kr && kr <= cg + ce) { s_selH = kc; s_resH = kr - cg; }
        }
    }
    if (!s_skipB) {
        const int kr = s_kr2L;
        for (int c = tid; c < mL; c += THREADS) {
            float fc = s_mini[2 * CAP - 1 - c];
            unsigned kc = f2key(fc);
            int cl = 0, ce = 0;
            for (int j = 0; j < mL; j++) {
                unsigned kj = f2key(s_mini[2 * CAP - 1 - j]);
                cl += (kj < kc);
                ce += (kj == kc);
            }
            if (cl + ce < kr) sumB += fc;                   // strictly below threshold
            if (cl < kr && kr <= cl + ce) { s_selL = kc; s_resL = kr - cl; }
        }
    }
    __syncthreads();

    // ---- block reduction + epilogue ------------------------------------------
    #pragma unroll
    for (int o = 16; o > 0; o >>= 1) {
        sumT += __shfl_xor_sync(0xFFFFFFFFu, sumT, o);
        sumB += __shfl_xor_sync(0xFFFFFFFFu, sumB, o);
    }
    if (lane == 0) { s_redf[0][wid] = sumT; s_redf[1][wid] = sumB; }
    __syncthreads();

    if (tid == 0) {
        float st = 0.0f, sb = 0.0f;
        #pragma unroll
        for (int w = 0; w < NWARP; ++w) { st += s_redf[0][w]; sb += s_redf[1][w]; }
        st += (float)s_resH * key2f(s_selH);    // exact tie handling
        sb += (float)s_resL * key2f(s_selL);
        out[blockIdx.x] = st / (float)kmax + (alpha / (float)kmin) * sb;
    }
}

// ================= GENERIC fallback (any n) — proven R8 path ================
#define GTHREADS 256

template<int NB, bool DESC>
__device__ __forceinline__ void resolve_small(const unsigned* __restrict__ hist, int krem,
                                              int lane, unsigned &bin, int &krem_out)
{
    constexpr int BPL = NB / 32;
    unsigned s = 0;
    #pragma unroll
    for (int j = 0; j < BPL; j++) {
        int b = DESC ? (NB - 1 - (lane * BPL + j)) : (lane * BPL + j);
        s += hist[b];
    }
    unsigned p = s;
    #pragma unroll
    for (int o = 1; o < 32; o <<= 1) {
        unsigned t = __shfl_up_sync(0xFFFFFFFFu, p, o);
        if (lane >= o) p += t;
    }
    unsigned excl = p - s;
    bool cross = (excl < (unsigned)krem) && (p >= (unsigned)krem);
    unsigned m = __ballot_sync(0xFFFFFFFFu, cross);
    int src = __ffs(m) - 1;
    unsigned bsel = 0; int k2 = 0;
    if (cross) {
        unsigned cum = excl;
        #pragma unroll
        for (int j = 0; j < BPL; j++) {
            int b = DESC ? (NB - 1 - (lane * BPL + j)) : (lane * BPL + j);
            unsigned c = hist[b];
            if (cum + c >= (unsigned)krem) { bsel = (unsigned)b; k2 = krem - (int)cum; break; }
            cum += c;
        }
    }
    bin = __shfl_sync(0xFFFFFFFFu, bsel, src);
    krem_out = __shfl_sync(0xFFFFFFFFu, k2, src);
}

template<bool DESC>
__device__ __forceinline__ void resolve_big(const unsigned* __restrict__ hist, int krem,
                                            int lane, unsigned &bin, int &krem_out)
{
    const uint4* h4 = (const uint4*)hist;
    unsigned s = 0;
    #pragma unroll
    for (int j = 0; j < 32; j++) {
        uint4 c = h4[lane * 32 + j];
        s += c.x + c.y + c.z + c.w;
    }
    unsigned p = s;
    if (DESC) {
        #pragma unroll
        for (int o = 1; o < 32; o <<= 1) {
            unsigned t = __shfl_down_sync(0xFFFFFFFFu, p, o);
            if (lane + o < 32) p += t;
        }
    } else {
        #pragma unroll
        for (int o = 1; o < 32; o <<= 1) {
            unsigned t = __shfl_up_sync(0xFFFFFFFFu, p, o);
            if (lane >= o) p += t;
        }
    }
    unsigned excl = p - s;
    bool cross = (excl < (unsigned)krem) && (p >= (unsigned)krem);
    unsigned m = __ballot_sync(0xFFFFFFFFu, cross);
    int src = __ffs(m) - 1;
    unsigned bsel = 0; int k2 = 0;
    if (cross) {
        unsigned cum = excl;
        if (DESC) {
            for (int b = lane * 128 + 127; b >= lane * 128; --b) {
                unsigned c = hist[b];
                if (cum + c >= (unsigned)krem) { bsel = (unsigned)b; k2 = krem - (int)cum; break; }
                cum += c;
            }
        } else {
            for (int b = lane * 128; b < lane * 128 + 128; ++b) {
                unsigned c = hist[b];
                if (cum + c >= (unsigned)krem) { bsel = (unsigned)b; k2 = krem - (int)cum; break; }
                cum += c;
            }
        }
    }
    bin = __shfl_sync(0xFFFFFFFFu, bsel, src);
    krem_out = __shfl_sync(0xFFFFFFFFu, k2, src);
}

__global__ void __launch_bounds__(GTHREADS, 8)
wildcat_generic(const float* __restrict__ x, float* __restrict__ out,
                int n, int kmax, int kmin, float alpha)
{
    __shared__ unsigned s_mem[4096];
    __shared__ unsigned s_subh[512];
    __shared__ unsigned s_selH, s_selL;
    __shared__ int      s_kremH, s_kremL, s_cntH, s_cntL;
    __shared__ float    s_red[2][GTHREADS / 32];
    float* s_val = (float*)s_mem;

    const int tid  = threadIdx.x;
    const int lane = tid & 31;
    const int wid  = tid >> 5;
    const float* __restrict__ xr = x + (long long)blockIdx.x * n;

    for (int b = tid; b < 4096; b += GTHREADS) s_mem[b] = 0;
    if (tid == 0) { s_cntH = 0; s_cntL = 0; }
    __syncthreads();

    for (int i = tid; i < n; i += GTHREADS)
        atomicAdd(&s_mem[f2key(xr[i]) >> 20], 1u);
    __syncthreads();

    if (wid == 0) {
        unsigned b; int k2;
        resolve_big<true>(s_mem, kmax, lane, b, k2);
        if (lane == 0) { s_selH = b; s_kremH = k2; }
    } else if (wid == 1) {
        unsigned b; int k2;
        resolve_big<false>(s_mem, kmin, lane, b, k2);
        if (lane == 0) { s_selL = b; s_kremL = k2; }
    }
    __syncthreads();
    const unsigned binH = s_selH, binL = s_selL;
    const bool sameBin = (binH == binL);
    __syncthreads();

    float sumT = 0.0f, sumB = 0.0f;
    for (int i = tid; i < n; i += GTHREADS) {
        float f = xr[i];
        unsigned b = f2key(f) >> 20;
        if (b > binH) sumT += f;
        if (b < binL) sumB += f;
        if (b == binH) { int p = atomicAdd(&s_cntH, 1); s_val[p] = f; }
        else if (b == binL) { int p = atomicAdd(&s_cntL, 1); s_val[4095 - p] = f; }
    }
    __syncthreads();
    const int cntH = min(s_cntH, 4096);
    const int cntL = sameBin ? cntH : min(s_cntL, 4096);

    #pragma unroll 1
    for (int l = 0; l < 3; l++) {
        const int fs = (l == 0) ? 20 : (l == 1) ? 12 : 6;
        const int sh = (l == 0) ? 12 : (l == 1) ? 6 : 0;
        const unsigned mk = (l == 0) ? 0xFFu : 0x3Fu;
        const int nb = (l == 0) ? 256 : 64;
        const unsigned pH = s_selH, pL = s_selL;
        if (tid < nb) { s_subh[tid] = 0; s_subh[tid + 256] = 0; }
        __syncthreads();
        for (int t = tid; t < cntH; t += GTHREADS) {
            unsigned key = f2key(s_val[t]);
            if ((key >> fs) == pH) atomicAdd(&s_subh[(key >> sh) & mk], 1u);
        }
        for (int t = tid; t < cntL; t += GTHREADS) {
            float f = sameBin ? s_val[t] : s_val[4095 - t];
            unsigned key = f2key(f);
            if ((key >> fs) == pL) atomicAdd(&s_subh[256 + ((key >> sh) & mk)], 1u);
        }
        __syncthreads();
        if (wid == 0) {
            unsigned b; int k2;
            if (nb == 256) resolve_small<256, true>(s_subh, s_kremH, lane, b, k2);
            else           resolve_small<64,  true>(s_subh, s_kremH, lane, b, k2);
            if (lane == 0) { s_selH = (pH << ((l == 0) ? 8 : 6)) | b; s_kremH = k2; }
        } else if (wid == 1) {
            unsigned b; int k2;
            if (nb == 256) resolve_small<256, false>(s_subh + 256, s_kremL, lane, b, k2);
            else           resolve_small<64,  false>(s_subh + 256, s_kremL, lane, b, k2);
            if (lane == 0) { s_selL = (pL << ((l == 0) ? 8 : 6)) | b; s_kremL = k2; }
        }
        __syncthreads();
    }

    const unsigned keyH = s_selH, keyL = s_selL;
    for (int t = tid; t < cntH; t += GTHREADS) {
        float f = s_val[t];
        if (f2key(f) > keyH) sumT += f;
    }
    for (int t = tid; t < cntL; t += GTHREADS) {
        float f = sameBin ? s_val[t] : s_val[4095 - t];
        if (f2key(f) < keyL) sumB += f;
    }
    #pragma unroll
    for (int o = 16; o > 0; o >>= 1) {
        sumT += __shfl_xor_sync(0xFFFFFFFFu, sumT, o);
        sumB += __shfl_xor_sync(0xFFFFFFFFu, sumB, o);
    }
    if (lane == 0) { s_red[0][wid] = sumT; s_red[1][wid] = sumB; }
    __syncthreads();
    if (tid == 0) {
        float st = 0.0f, sb = 0.0f;
        #pragma unroll
        for (int w = 0; w < GTHREADS / 32; ++w) { st += s_red[0][w]; sb += s_red[1][w]; }
        st += (float)s_kremH * key2f(keyH);
        sb += (float)s_kremL * key2f(keyL);
        out[blockIdx.x] = st / (float)kmax + (alpha / (float)kmin) * sb;
    }
}

extern "C" void kernel_launch(void* const* d_in, const int* in_sizes, int n_in,
                              void* d_out, int out_size)
{
    const float* x = (const float*)d_in[0];
    float* out = (float*)d_out;

    const int rows = out_size;                 // 32*512 = 16384
    const int n = in_sizes[0] / rows;          // 4096
    int kmax = (int)lrintf(0.2f * (float)n);   // int(round(0.2*n)) = 819
    int kmin = (int)lrintf(0.2f * (float)n);
    if (kmax < 1) kmax = 1;
    if (kmin < 1) kmin = 1;

    if (n == NFAST)
        wildcat_fast<<<rows, THREADS>>>(x, out, kmax, kmin, 0.7f);
    else
        wildcat_generic<<<rows, GTHREADS>>>(x, out, n, kmax, kmin, 0.7f);
}

// round 17
// speedup vs baseline: 1.8094x; 1.4499x over previous
#include <cuda_runtime.h>
#include <math.h>

#define THREADS 256
#define ELEMS   16
#define NFAST   (THREADS * ELEMS)   // 4096
#define CAP     512                 // bracket candidate cap per side
#define NWARP   (THREADS / 32)

// Order-preserving float->uint key: monotonic increasing with float value.
__device__ __forceinline__ unsigned f2key(float v) {
    unsigned u = __float_as_uint(v);
    return u ^ (unsigned)(((int)u >> 31) | 0x80000000u);
}
__device__ __forceinline__ float key2f(unsigned key) {
    unsigned u = (key & 0x80000000u) ? (key ^ 0x80000000u) : ~key;
    return __uint_as_float(u);
}

// ========================= FAST kernel (n == 4096) ==========================
__global__ void __launch_bounds__(THREADS, 6)
wildcat_fast(const float* __restrict__ x, float* __restrict__ out,
             int kmax, int kmin, float alpha)
{
    __shared__ float     s_cand[2 * CAP];   // bracket candidates: top from 0, bottom from end
    __shared__ float     s_mini[2 * CAP];   // threshold-sub-bin elements
    __shared__ unsigned  s_hT[16], s_hB[16];
    __shared__ unsigned  s_cA, s_cB, s_c2[2];
    __shared__ int       s_cntH, s_cntL, s_mH, s_mL;
    __shared__ int       s_krH, s_krL, s_kr2H, s_kr2L;
    __shared__ int       s_selBinT, s_selBinB;
    __shared__ int       s_missT, s_missB, s_skipT, s_skipB, s_refine;
    __shared__ long long s_fb[4];           // loT, hiT, loB, hiB (fallback key bounds)
    __shared__ int       s_fc[4];           // cAloT, cAhiT, cBloB, cBhiB
    __shared__ unsigned  s_selH, s_selL;
    __shared__ int       s_resH, s_resL;
    __shared__ float     s_redf[2][NWARP];

    const int tid  = threadIdx.x;
    const int lane = tid & 31;
    const int wid  = tid >> 5;
    const float* __restrict__ xr = x + (long long)blockIdx.x * NFAST;

    // ---- load 16 elements into registers (the only full-row memory pass) ----
    float v[ELEMS];
    {
        const float4* __restrict__ xr4 = (const float4*)xr;
        #pragma unroll
        for (int k = 0; k < 4; k++) {
            float4 t = xr4[tid + k * THREADS];
            v[4 * k + 0] = t.x; v[4 * k + 1] = t.y;
            v[4 * k + 2] = t.z; v[4 * k + 3] = t.w;
        }
    }
    if (tid < 16) s_hT[tid] = 0;
    else if (tid < 32) s_hB[tid - 16] = 0;
    if (tid == 0) {
        s_cA = 0; s_cB = 0; s_cntH = 0; s_cntL = 0; s_mH = 0; s_mL = 0;
        s_skipT = 0; s_skipB = 0;
    }
    __syncthreads();

    const float PT_HI = 0.94f, PT_LO = 0.74f;      // top bracket (PT_LO, PT_HI]
    const float PB_LO = -0.94f, PB_HI = -0.74f;    // bottom bracket [PB_LO, PB_HI)

    // ===== single fused sweep: branchless flags + QUAD-BATCHED appends ========
    float sumT = 0.0f, sumB = 0.0f;
    {
        unsigned cA = 0, cB = 0;
        #pragma unroll
        for (int q = 0; q < ELEMS; q += 4) {
            bool iH[4], iL[4];
            int cH = 0, cL = 0;
            #pragma unroll
            for (int j = 0; j < 4; j++) {
                float f = v[q + j];
                bool aT = f > PT_HI;
                bool aB = f < PB_LO;
                if (aT) { sumT += f; cA++; }
                if (aB) { sumB += f; cB++; }
                iH[j] = (f > PT_LO) && !aT;
                iL[j] = (f < PB_HI) && !aB;
                cH += iH[j]; cL += iL[j];
            }
            if (cH) {                                  // one branch + one atomic per quad
                int p = atomicAdd(&s_cntH, cH);
                #pragma unroll
                for (int j = 0; j < 4; j++)
                    if (iH[j]) { if (p < CAP) s_cand[p] = v[q + j]; p++; }
            }
            if (cL) {
                int p = atomicAdd(&s_cntL, cL);
                #pragma unroll
                for (int j = 0; j < 4; j++)
                    if (iL[j]) { if (p < CAP) s_cand[2 * CAP - 1 - p] = v[q + j]; p++; }
            }
        }
        cA = __reduce_add_sync(0xFFFFFFFFu, cA);
        cB = __reduce_add_sync(0xFFFFFFFFu, cB);
        if (lane == 0) { atomicAdd(&s_cA, cA); atomicAdd(&s_cB, cB); }
    }
    __syncthreads();

    // ---- exact rank check: does the kth element land inside the bracket? ----
    if (tid == 0) {
        int kr = kmax - (int)s_cA;
        s_krH = kr;
        s_missT = (kr <= 0 || kr > s_cntH || s_cntH > CAP) ? 1 : 0;
    }
    if (tid == 32) {
        int kr = kmin - (int)s_cB;
        s_krL = kr;
        s_missB = (kr <= 0 || kr > s_cntL || s_cntL > CAP) ? 1 : 0;
    }
    __syncthreads();

    const int cnH = min(s_cntH, CAP), cnL = min(s_cntL, CAP);
    const int missT = s_missT, missB = s_missB;

    // ===== sub-bin histogram over candidates (16 bins, arithmetic binning) ====
    if (!missT) {
        for (int c = tid; c < cnH; c += THREADS) {
            float f = s_cand[c];
            int b = (int)((f - PT_LO) * 80.0f); b = max(0, min(15, b));
            atomicAdd(&s_hT[b], 1u);
        }
    }
    if (!missB) {
        for (int c = tid; c < cnL; c += THREADS) {
            float f = s_cand[2 * CAP - 1 - c];
            int b = (int)((f - PB_LO) * 80.0f); b = max(0, min(15, b));
            atomicAdd(&s_hB[b], 1u);
        }
    }
    __syncthreads();
    if (tid == 0 && !missT) {
        int kr = s_krH, cum = 0, sel = 0, kr2 = kr;
        for (int b = 15; b >= 0; --b) {
            int c = (int)s_hT[b];
            if (cum + c >= kr) { sel = b; kr2 = kr - cum; break; }
            cum += c;
        }
        s_selBinT = sel; s_kr2H = kr2;
    }
    if (tid == 32 && !missB) {
        int kr = s_krL, cum = 0, sel = 15, kr2 = kr;
        for (int b = 0; b < 16; ++b) {
            int c = (int)s_hB[b];
            if (cum + c >= kr) { sel = b; kr2 = kr - cum; break; }
            cum += c;
        }
        s_selBinB = sel; s_kr2L = kr2;
    }
    __syncthreads();

    // ===== mini pass: bank above/below-sub-bin sums, gather threshold sub-bin =
    if (!missT) {
        const int sel = s_selBinT;
        for (int c = tid; c < cnH; c += THREADS) {
            float f = s_cand[c];
            int b = (int)((f - PT_LO) * 80.0f); b = max(0, min(15, b));
            if (b > sel) sumT += f;
            else if (b == sel) { int p = atomicAdd(&s_mH, 1); s_mini[p] = f; }
        }
    }
    if (!missB) {
        const int sel = s_selBinB;
        for (int c = tid; c < cnL; c += THREADS) {
            float f = s_cand[2 * CAP - 1 - c];
            int b = (int)((f - PB_LO) * 80.0f); b = max(0, min(15, b));
            if (b < sel) sumB += f;
            else if (b == sel) { int p = atomicAdd(&s_mL, 1); s_mini[2 * CAP - 1 - p] = f; }
        }
    }

    // ===== exact key-space fallback for missed sides (cold, block-uniform) ====
    if (missT || missB) {
        if (tid == 0) {
            s_fb[0] = -1; s_fb[1] = 0xFFFFFFFFLL;  s_fc[0] = NFAST; s_fc[1] = 0;
            s_fb[2] = 0;  s_fb[3] = 0x100000000LL; s_fc[2] = 0;     s_fc[3] = NFAST;
            s_refine = 1;
        }
        __syncthreads();
        while (s_refine) {
            if (tid < 2) s_c2[tid] = 0;
            const long long midT = (s_fb[0] + s_fb[1]) >> 1;
            const long long midB = (s_fb[2] + s_fb[3]) >> 1;
            __syncthreads();
            unsigned ct = 0, cb = 0;
            #pragma unroll
            for (int j = 0; j < ELEMS; j++) {
                long long k = (long long)f2key(v[j]);
                ct += (k > midT);
                cb += (k < midB);
            }
            ct = __reduce_add_sync(0xFFFFFFFFu, ct);
            cb = __reduce_add_sync(0xFFFFFFFFu, cb);
            if (lane == 0) { atomicAdd(&s_c2[0], ct); atomicAdd(&s_c2[1], cb); }
            __syncthreads();
            if (tid == 0) {
                if (missT && (s_fc[0] - s_fc[1] > CAP) && (s_fb[1] - s_fb[0] > 1)) {
                    int c = (int)s_c2[0];
                    if (c >= kmax) { s_fb[0] = midT; s_fc[0] = c; }
                    else           { s_fb[1] = midT; s_fc[1] = c; }
                }
                if (missB && (s_fc[3] - s_fc[2] > CAP) && (s_fb[3] - s_fb[2] > 1)) {
                    int c = (int)s_c2[1];
                    if (c >= kmin) { s_fb[3] = midB; s_fc[3] = c; }
                    else           { s_fb[2] = midB; s_fc[2] = c; }
                }
                bool nT = missT && (s_fc[0] - s_fc[1] > CAP) && (s_fb[1] - s_fb[0] > 1);
                bool nB = missB && (s_fc[3] - s_fc[2] > CAP) && (s_fb[3] - s_fb[2] > 1);
                s_refine = (nT || nB) ? 1 : 0;
            }
            __syncthreads();
        }
        if (missT) {
            sumT = 0.0f;                               // recompute side exactly
            const long long lo = s_fb[0], hi = s_fb[1];
            const bool w1 = (hi - lo) == 1;
            if (tid == 0) {
                s_kr2H = kmax - s_fc[1];
                if (w1) { s_skipT = 1; s_selH = (unsigned)hi; s_resH = kmax - s_fc[1]; }
            }
            #pragma unroll
            for (int j = 0; j < ELEMS; j++) {
                float f = v[j];
                long long k = (long long)f2key(f);
                if (k > hi) sumT += f;
                else if (!w1 && k > lo) { int p = atomicAdd(&s_mH, 1); if (p < CAP) s_mini[p] = f; }
            }
        }
        if (missB) {
            sumB = 0.0f;
            const long long lo = s_fb[2], hi = s_fb[3];
            const bool w1 = (hi - lo) == 1;
            if (tid == 0) {
                s_kr2L = kmin - s_fc[2];
                if (w1) { s_skipB = 1; s_selL = (unsigned)lo; s_resL = kmin - s_fc[2]; }
            }
            #pragma unroll
            for (int j = 0; j < ELEMS; j++) {
                float f = v[j];
                long long k = (long long)f2key(f);
                if (k < lo) sumB += f;
                else if (!w1 && k < hi) { int p = atomicAdd(&s_mL, 1); if (p < CAP) s_mini[2 * CAP - 1 - p] = f; }
            }
        }
    }
    __syncthreads();

    // ===== quadratic rank-select over mini lists (~15-25 elements) ============
    const int mH = min(s_mH, CAP), mL = min(s_mL, CAP);
    if (!s_skipT) {
        const int kr = s_kr2H;
        for (int c = tid; c < mH; c += THREADS) {
            float fc = s_mini[c];
            unsigned kc = f2key(fc);
            int cg = 0, ce = 0;
            for (int j = 0; j < mH; j++) {
                unsigned kj = f2key(s_mini[j]);
                cg += (kj > kc);
                ce += (kj == kc);
            }
            if (cg + ce < kr) sumT += fc;                   // strictly above threshold
            if (cg < kr && kr <= cg + ce) { s_selH = kc; s_resH = kr - cg; }
        }
    }
    if (!s_skipB) {
        const int kr = s_kr2L;
        for (int c = tid; c < mL; c += THREADS) {
            float fc = s_mini[2 * CAP - 1 - c];
            unsigned kc = f2key(fc);
            int cl = 0, ce = 0;
            for (int j = 0; j < mL; j++) {
                unsigned kj = f2key(s_mini[2 * CAP - 1 - j]);
                cl += (kj < kc);
                ce += (kj == kc);
            }
            if (cl + ce < kr) sumB += fc;                   // strictly below threshold
            if (cl < kr && kr <= cl + ce) { s_selL = kc; s_resL = kr - cl; }
        }
    }
    __syncthreads();

    // ---- block reduction + epilogue ------------------------------------------
    #pragma unroll
    for (int o = 16; o > 0; o >>= 1) {
        sumT += __shfl_xor_sync(0xFFFFFFFFu, sumT, o);
        sumB += __shfl_xor_sync(0xFFFFFFFFu, sumB, o);
    }
    if (lane == 0) { s_redf[0][wid] = sumT; s_redf[1][wid] = sumB; }
    __syncthreads();

    if (tid == 0) {
        float st = 0.0f, sb = 0.0f;
        #pragma unroll
        for (int w = 0; w < NWARP; ++w) { st += s_redf[0][w]; sb += s_redf[1][w]; }
        st += (float)s_resH * key2f(s_selH);    // exact tie handling
        sb += (float)s_resL * key2f(s_selL);
        out[blockIdx.x] = st / (float)kmax + (alpha / (float)kmin) * sb;
    }
}

// ================= GENERIC fallback (any n) — proven R8 path ================
#define GTHREADS 256

template<int NB, bool DESC>
__device__ __forceinline__ void resolve_small(const unsigned* __restrict__ hist, int krem,
                                              int lane, unsigned &bin, int &krem_out)
{
    constexpr int BPL = NB / 32;
    unsigned s = 0;
    #pragma unroll
    for (int j = 0; j < BPL; j++) {
        int b = DESC ? (NB - 1 - (lane * BPL + j)) : (lane * BPL + j);
        s += hist[b];
    }
    unsigned p = s;
    #pragma unroll
    for (int o = 1; o < 32; o <<= 1) {
        unsigned t = __shfl_up_sync(0xFFFFFFFFu, p, o);
        if (lane >= o) p += t;
    }
    unsigned excl = p - s;
    bool cross = (excl < (unsigned)krem) && (p >= (unsigned)krem);
    unsigned m = __ballot_sync(0xFFFFFFFFu, cross);
    int src = __ffs(m) - 1;
    unsigned bsel = 0; int k2 = 0;
    if (cross) {
        unsigned cum = excl;
        #pragma unroll
        for (int j = 0; j < BPL; j++) {
            int b = DESC ? (NB - 1 - (lane * BPL + j)) : (lane * BPL + j);
            unsigned c = hist[b];
            if (cum + c >= (unsigned)krem) { bsel = (unsigned)b; k2 = krem - (int)cum; break; }
            cum += c;
        }
    }
    bin = __shfl_sync(0xFFFFFFFFu, bsel, src);
    krem_out = __shfl_sync(0xFFFFFFFFu, k2, src);
}

template<bool DESC>
__device__ __forceinline__ void resolve_big(const unsigned* __restrict__ hist, int krem,
                                            int lane, unsigned &bin, int &krem_out)
{
    const uint4* h4 = (const uint4*)hist;
    unsigned s = 0;
    #pragma unroll
    for (int j = 0; j < 32; j++) {
        uint4 c = h4[lane * 32 + j];
        s += c.x + c.y + c.z + c.w;
    }
    unsigned p = s;
    if (DESC) {
        #pragma unroll
        for (int o = 1; o < 32; o <<= 1) {
            unsigned t = __shfl_down_sync(0xFFFFFFFFu, p, o);
            if (lane + o < 32) p += t;
        }
    } else {
        #pragma unroll
        for (int o = 1; o < 32; o <<= 1) {
            unsigned t = __shfl_up_sync(0xFFFFFFFFu, p, o);
            if (lane >= o) p += t;
        }
    }
    unsigned excl = p - s;
    bool cross = (excl < (unsigned)krem) && (p >= (unsigned)krem);
    unsigned m = __ballot_sync(0xFFFFFFFFu, cross);
    int src = __ffs(m) - 1;
    unsigned bsel = 0; int k2 = 0;
    if (cross) {
        unsigned cum = excl;
        if (DESC) {
            for (int b = lane * 128 + 127; b >= lane * 128; --b) {
                unsigned c = hist[b];
                if (cum + c >= (unsigned)krem) { bsel = (unsigned)b; k2 = krem - (int)cum; break; }
                cum += c;
            }
        } else {
            for (int b = lane * 128; b < lane * 128 + 128; ++b) {
                unsigned c = hist[b];
                if (cum + c >= (unsigned)krem) { bsel = (unsigned)b; k2 = krem - (int)cum; break; }
                cum += c;
            }
        }
    }
    bin = __shfl_sync(0xFFFFFFFFu, bsel, src);
    krem_out = __shfl_sync(0xFFFFFFFFu, k2, src);
}

__global__ void __launch_bounds__(GTHREADS, 8)
wildcat_generic(const float* __restrict__ x, float* __restrict__ out,
                int n, int kmax, int kmin, float alpha)
{
    __shared__ unsigned s_mem[4096];
    __shared__ unsigned s_subh[512];
    __shared__ unsigned s_selH, s_selL;
    __shared__ int      s_kremH, s_kremL, s_cntH, s_cntL;
    __shared__ float    s_red[2][GTHREADS / 32];
    float* s_val = (float*)s_mem;

    const int tid  = threadIdx.x;
    const int lane = tid & 31;
    const int wid  = tid >> 5;
    const float* __restrict__ xr = x + (long long)blockIdx.x * n;

    for (int b = tid; b < 4096; b += GTHREADS) s_mem[b] = 0;
    if (tid == 0) { s_cntH = 0; s_cntL = 0; }
    __syncthreads();

    for (int i = tid; i < n; i += GTHREADS)
        atomicAdd(&s_mem[f2key(xr[i]) >> 20], 1u);
    __syncthreads();

    if (wid == 0) {
        unsigned b; int k2;
        resolve_big<true>(s_mem, kmax, lane, b, k2);
        if (lane == 0) { s_selH = b; s_kremH = k2; }
    } else if (wid == 1) {
        unsigned b; int k2;
        resolve_big<false>(s_mem, kmin, lane, b, k2);
        if (lane == 0) { s_selL = b; s_kremL = k2; }
    }
    __syncthreads();
    const unsigned binH = s_selH, binL = s_selL;
    const bool sameBin = (binH == binL);
    __syncthreads();

    float sumT = 0.0f, sumB = 0.0f;
    for (int i = tid; i < n; i += GTHREADS) {
        float f = xr[i];
        unsigned b = f2key(f) >> 20;
        if (b > binH) sumT += f;
        if (b < binL) sumB += f;
        if (b == binH) { int p = atomicAdd(&s_cntH, 1); s_val[p] = f; }
        else if (b == binL) { int p = atomicAdd(&s_cntL, 1); s_val[4095 - p] = f; }
    }
    __syncthreads();
    const int cntH = min(s_cntH, 4096);
    const int cntL = sameBin ? cntH : min(s_cntL, 4096);

    #pragma unroll 1
    for (int l = 0; l < 3; l++) {
        const int fs = (l == 0) ? 20 : (l == 1) ? 12 : 6;
        const int sh = (l == 0) ? 12 : (l == 1) ? 6 : 0;
        const unsigned mk = (l == 0) ? 0xFFu : 0x3Fu;
        const int nb = (l == 0) ? 256 : 64;
        const unsigned pH = s_selH, pL = s_selL;
        if (tid < nb) { s_subh[tid] = 0; s_subh[tid + 256] = 0; }
        __syncthreads();
        for (int t = tid; t < cntH; t += GTHREADS) {
            unsigned key = f2key(s_val[t]);
            if ((key >> fs) == pH) atomicAdd(&s_subh[(key >> sh) & mk], 1u);
        }
        for (int t = tid; t < cntL; t += GTHREADS) {
            float f = sameBin ? s_val[t] : s_val[4095 - t];
            unsigned key = f2key(f);
            if ((key >> fs) == pL) atomicAdd(&s_subh[256 + ((key >> sh) & mk)], 1u);
        }
        __syncthreads();
        if (wid == 0) {
            unsigned b; int k2;
            if (nb == 256) resolve_small<256, true>(s_subh, s_kremH, lane, b, k2);
            else           resolve_small<64,  true>(s_subh, s_kremH, lane, b, k2);
            if (lane == 0) { s_selH = (pH << ((l == 0) ? 8 : 6)) | b; s_kremH = k2; }
        } else if (wid == 1) {
            unsigned b; int k2;
            if (nb == 256) resolve_small<256, false>(s_subh + 256, s_kremL, lane, b, k2);
            else           resolve_small<64,  false>(s_subh + 256, s_kremL, lane, b, k2);
            if (lane == 0) { s_selL = (pL << ((l == 0) ? 8 : 6)) | b; s_kremL = k2; }
        }
        __syncthreads();
    }

    const unsigned keyH = s_selH, keyL = s_selL;
    for (int t = tid; t < cntH; t += GTHREADS) {
        float f = s_val[t];
        if (f2key(f) > keyH) sumT += f;
    }
    for (int t = tid; t < cntL; t += GTHREADS) {
        float f = sameBin ? s_val[t] : s_val[4095 - t];
        if (f2key(f) < keyL) sumB += f;
    }
    #pragma unroll
    for (int o = 16; o > 0; o >>= 1) {
        sumT += __shfl_xor_sync(0xFFFFFFFFu, sumT, o);
        sumB += __shfl_xor_sync(0xFFFFFFFFu, sumB, o);
    }
    if (lane == 0) { s_red[0][wid] = sumT; s_red[1][wid] = sumB; }
    __syncthreads();
    if (tid == 0) {
        float st = 0.0f, sb = 0.0f;
        #pragma unroll
        for (int w = 0; w < GTHREADS / 32; ++w) { st += s_red[0][w]; sb += s_red[1][w]; }
        st += (float)s_kremH * key2f(keyH);
        sb += (float)s_kremL * key2f(keyL);
        out[blockIdx.x] = st / (float)kmax + (alpha / (float)kmin) * sb;
    }
}

extern "C" void kernel_launch(void* const* d_in, const int* in_sizes, int n_in,
                              void* d_out, int out_size)
{
    const float* x = (const float*)d_in[0];
    float* out = (float*)d_out;

    const int rows = out_size;                 // 32*512 = 16384
    const int n = in_sizes[0] / rows;          // 4096
    int kmax = (int)lrintf(0.2f * (float)n);   // int(round(0.2*n)) = 819
    int kmin = (int)lrintf(0.2f * (float)n);
    if (kmax < 1) kmax = 1;
    if (kmin < 1) kmin = 1;

    if (n == NFAST)
        wildcat_fast<<<rows, THREADS>>>(x, out, kmax, kmin, 0.7f);
    else
        wildcat_generic<<<rows, GTHREADS>>>(x, out, n, kmax, kmin, 0.7f);
}